// round 2
// baseline (speedup 1.0000x reference)
#include <cuda_runtime.h>
#include <cstdint>
#include <cmath>

#define NTOK 8192       // B*S = 4*2048
#define DDIM 1024
#define FDIM 4096
#define NEXP 4
#define NSLOT (NTOK * 2)

// ---- device scratch (module-load allocation; no runtime alloc) ----
__device__ int   g_count[NEXP];
__device__ int   g_list[NEXP][NTOK];            // slot ids: token*2 + k
__device__ float g_h[(size_t)NSLOT * FDIM];     // 256 MB: swish(x@W1+b1) per slot
__device__ float g_y[(size_t)NSLOT * DDIM];     // 64 MB:  h@W2+b2 per slot

// ---------------------------------------------------------------
__global__ void k_reset() {
    if (threadIdx.x < NEXP) g_count[threadIdx.x] = 0;
}

// One block (128 threads) per token: 4 dot products of length 1024, top-2.
__global__ void k_gate(const float* __restrict__ x,
                       const float* __restrict__ Wg,
                       const float* __restrict__ bg) {
    int t   = blockIdx.x;
    int tid = threadIdx.x;
    const float* xr = x + (size_t)t * DDIM;

    float s0 = 0.f, s1 = 0.f, s2 = 0.f, s3 = 0.f;
    for (int i = tid; i < DDIM; i += 128) {
        float xv = xr[i];
        float4 w = *reinterpret_cast<const float4*>(Wg + (size_t)i * 4);
        s0 += xv * w.x; s1 += xv * w.y; s2 += xv * w.z; s3 += xv * w.w;
    }
    #pragma unroll
    for (int o = 16; o; o >>= 1) {
        s0 += __shfl_down_sync(0xffffffffu, s0, o);
        s1 += __shfl_down_sync(0xffffffffu, s1, o);
        s2 += __shfl_down_sync(0xffffffffu, s2, o);
        s3 += __shfl_down_sync(0xffffffffu, s3, o);
    }
    __shared__ float red[4][4];
    int w = tid >> 5;
    if ((tid & 31) == 0) {
        red[w][0] = s0; red[w][1] = s1; red[w][2] = s2; red[w][3] = s3;
    }
    __syncthreads();
    if (tid == 0) {
        float l[4];
        #pragma unroll
        for (int e = 0; e < 4; e++)
            l[e] = red[0][e] + red[1][e] + red[2][e] + red[3][e] + bg[e];
        // argmax (ties -> lowest index, matching jax top_k semantics)
        int e0 = 0;
        #pragma unroll
        for (int e = 1; e < 4; e++) if (l[e] > l[e0]) e0 = e;
        int e1 = -1;
        #pragma unroll
        for (int e = 0; e < 4; e++) {
            if (e == e0) continue;
            if (e1 < 0 || l[e] > l[e1]) e1 = e;
        }
        int p0 = atomicAdd(&g_count[e0], 1);
        g_list[e0][p0] = t * 2;
        int p1 = atomicAdd(&g_count[e1], 1);
        g_list[e1][p1] = t * 2 + 1;
    }
}

// ---------------------------------------------------------------
// Grouped SGEMM: C[slot] = act(A[row(slot)] @ B_e + bias_e)
//   SWISH=true : A = x (row = slot>>1 = token), act = silu, C = g_h
//   SWISH=false: A = g_h (row = slot),          act = id,   C = g_y
// Tile 128x128, K-step 16, 256 threads, 8x8 per thread.
template <int KDIM, int NDIM, bool SWISH>
__global__ void k_gemm(const float* __restrict__ A,
                       const float* __restrict__ Bw,
                       const float* __restrict__ bias,
                       float* __restrict__ Cout) {
    int e = blockIdx.z;
    int n = g_count[e];
    int row0 = blockIdx.x * 128;
    if (row0 >= n) return;
    int col0 = blockIdx.y * 128;

    const float* B  = Bw + (size_t)e * KDIM * NDIM + col0;
    const float* bv = bias + (size_t)e * NDIM + col0;
    const int* lst  = g_list[e];

    __shared__ float As[16][128];
    __shared__ float Bs[16][128];

    int tid = threadIdx.x;
    int ty = tid >> 4, tx = tid & 15;

    // A-load mapping: this thread owns local row tid>>1, k-offset (tid&1)*8
    int lrow = tid >> 1;
    int gr = row0 + lrow;
    if (gr >= n) gr = n - 1;               // clamp (store predicated later)
    int entry = lst[gr];
    int arow  = SWISH ? (entry >> 1) : entry;
    const float* aptr = A + (size_t)arow * KDIM + (size_t)((tid & 1) * 8);
    int kof = (tid & 1) * 8;

    // B-load mapping: k-row tid>>4, 8 consecutive cols (tid&15)*8 .. +7
    const float* bptr = B + (size_t)(tid >> 4) * NDIM + (size_t)((tid & 15) * 8);

    float acc[8][8];
    #pragma unroll
    for (int i = 0; i < 8; i++)
        #pragma unroll
        for (int j = 0; j < 8; j++) acc[i][j] = 0.f;

    for (int k0 = 0; k0 < KDIM; k0 += 16) {
        float4 a0 = *reinterpret_cast<const float4*>(aptr + k0);
        float4 a1 = *reinterpret_cast<const float4*>(aptr + k0 + 4);
        const float* bp = bptr + (size_t)k0 * NDIM;
        float4 b0 = *reinterpret_cast<const float4*>(bp);
        float4 b1 = *reinterpret_cast<const float4*>(bp + 4);   // FIXED: next 4 cols

        __syncthreads();   // prior compute done before overwrite
        As[kof + 0][lrow] = a0.x; As[kof + 1][lrow] = a0.y;
        As[kof + 2][lrow] = a0.z; As[kof + 3][lrow] = a0.w;
        As[kof + 4][lrow] = a1.x; As[kof + 5][lrow] = a1.y;
        As[kof + 6][lrow] = a1.z; As[kof + 7][lrow] = a1.w;
        *reinterpret_cast<float4*>(&Bs[tid >> 4][(tid & 15) * 8])     = b0;
        *reinterpret_cast<float4*>(&Bs[tid >> 4][(tid & 15) * 8 + 4]) = b1;
        __syncthreads();

        #pragma unroll
        for (int k = 0; k < 16; k++) {
            float4 av0 = *reinterpret_cast<const float4*>(&As[k][ty * 8]);
            float4 av1 = *reinterpret_cast<const float4*>(&As[k][ty * 8 + 4]);
            float4 bv0 = *reinterpret_cast<const float4*>(&Bs[k][tx * 8]);
            float4 bv1 = *reinterpret_cast<const float4*>(&Bs[k][tx * 8 + 4]);
            float a[8] = {av0.x, av0.y, av0.z, av0.w, av1.x, av1.y, av1.z, av1.w};
            float b[8] = {bv0.x, bv0.y, bv0.z, bv0.w, bv1.x, bv1.y, bv1.z, bv1.w};
            #pragma unroll
            for (int i = 0; i < 8; i++)
                #pragma unroll
                for (int j = 0; j < 8; j++)
                    acc[i][j] = fmaf(a[i], b[j], acc[i][j]);
        }
    }

    // epilogue: bias + (optional) swish, scatter to slot rows
    #pragma unroll
    for (int i = 0; i < 8; i++) {
        int r = row0 + ty * 8 + i;
        if (r >= n) break;
        int ent = lst[r];
        float* cp = Cout + (size_t)ent * NDIM + col0 + tx * 8;
        float v[8];
        #pragma unroll
        for (int j = 0; j < 8; j++) {
            float c = acc[i][j] + bv[tx * 8 + j];
            if (SWISH) c = c / (1.0f + expf(-c));   // silu
            v[j] = c;
        }
        *reinterpret_cast<float4*>(cp)     = make_float4(v[0], v[1], v[2], v[3]);
        *reinterpret_cast<float4*>(cp + 4) = make_float4(v[4], v[5], v[6], v[7]);
    }
}

// out[t] = y[2t] + y[2t+1]  (deterministic combine, float4 granularity)
__global__ void k_combine(float* __restrict__ out) {
    int i = blockIdx.x * blockDim.x + threadIdx.x;
    if (i >= NTOK * DDIM / 4) return;
    int t = i >> 8;              // DDIM/4 = 256
    int d = i & 255;
    const float4* y = reinterpret_cast<const float4*>(g_y);
    float4 a = y[(size_t)(2 * t) * 256 + d];
    float4 b = y[(size_t)(2 * t + 1) * 256 + d];
    reinterpret_cast<float4*>(out)[i] =
        make_float4(a.x + b.x, a.y + b.y, a.z + b.z, a.w + b.w);
}

// ---------------------------------------------------------------
extern "C" void kernel_launch(void* const* d_in, const int* in_sizes, int n_in,
                              void* d_out, int out_size) {
    const float* x  = (const float*)d_in[0];
    const float* Wg = (const float*)d_in[1];
    const float* bg = (const float*)d_in[2];
    const float* W1 = (const float*)d_in[3];
    const float* b1 = (const float*)d_in[4];
    const float* W2 = (const float*)d_in[5];
    const float* b2 = (const float*)d_in[6];
    float* out = (float*)d_out;

    float* hptr = nullptr;
    float* yptr = nullptr;
    cudaGetSymbolAddress((void**)&hptr, g_h);
    cudaGetSymbolAddress((void**)&yptr, g_y);

    k_reset<<<1, 32>>>();
    k_gate<<<NTOK, 128>>>(x, Wg, bg);

    dim3 g1(NTOK / 128, FDIM / 128, NEXP);   // (64, 32, 4)
    k_gemm<DDIM, FDIM, true><<<g1, 256>>>(x, W1, b1, hptr);

    dim3 g2(NTOK / 128, DDIM / 128, NEXP);   // (64, 8, 4)
    k_gemm<FDIM, DDIM, false><<<g2, 256>>>(hptr, W2, b2, yptr);

    int nvec = NTOK * DDIM / 4;
    k_combine<<<(nvec + 255) / 256, 256>>>(out);
}

// round 4
// speedup vs baseline: 1.9701x; 1.9701x over previous
#include <cuda_runtime.h>
#include <cuda_bf16.h>
#include <cstdint>
#include <cmath>

#define NTOK 8192       // B*S
#define DDIM 1024
#define FDIM 4096
#define NEXP 4
#define NSLOT (NTOK * 2)
#define RPAD (NSLOT + 128 * NEXP)   // 16896: per-expert 128-aligned packed rows

// ---------------- device scratch (module-load; no runtime alloc) ------------
__device__ int g_count[NEXP];
__device__ int g_list[NEXP][NTOK];
__device__ int g_off[NEXP + 1];
__device__ int g_rowslot[RPAD];
__device__ __nv_bfloat16 g_ahi[(size_t)RPAD * DDIM];
__device__ __nv_bfloat16 g_alo[(size_t)RPAD * DDIM];
__device__ __nv_bfloat16 g_hhi[(size_t)RPAD * FDIM];
__device__ __nv_bfloat16 g_hlo[(size_t)RPAD * FDIM];
__device__ __nv_bfloat16 g_w1hi[(size_t)NEXP * FDIM * DDIM];  // [E][F][D]
__device__ __nv_bfloat16 g_w1lo[(size_t)NEXP * FDIM * DDIM];
__device__ __nv_bfloat16 g_w2hi[(size_t)NEXP * DDIM * FDIM];  // [E][D][F]
__device__ __nv_bfloat16 g_w2lo[(size_t)NEXP * DDIM * FDIM];
__device__ float g_y[(size_t)NSLOT * DDIM];

// ---------------- helpers ----------------------------------------------------
__device__ __forceinline__ uint32_t smem_u32(const void* p) {
    uint32_t a;
    asm("{ .reg .u64 t; cvta.to.shared.u64 t, %1; cvt.u32.u64 %0, t; }" : "=r"(a) : "l"(p));
    return a;
}
#define CP_ASYNC16(dst, src) \
    asm volatile("cp.async.cg.shared.global [%0], [%1], 16;" :: "r"(dst), "l"(src))
#define CP_COMMIT() asm volatile("cp.async.commit_group;" ::: "memory")
#define CP_WAIT1()  asm volatile("cp.async.wait_group 1;" ::: "memory")
#define CP_WAIT0()  asm volatile("cp.async.wait_group 0;" ::: "memory")

__device__ __forceinline__ void ldm_x4(uint32_t* r, uint32_t addr) {
    asm volatile("ldmatrix.sync.aligned.m8n8.x4.shared.b16 {%0,%1,%2,%3}, [%4];"
                 : "=r"(r[0]), "=r"(r[1]), "=r"(r[2]), "=r"(r[3]) : "r"(addr));
}
__device__ __forceinline__ void mma16816(float* c, const uint32_t* a, uint32_t b0, uint32_t b1) {
    asm volatile("mma.sync.aligned.m16n8k16.row.col.f32.bf16.bf16.f32 "
                 "{%0,%1,%2,%3}, {%4,%5,%6,%7}, {%8,%9}, {%0,%1,%2,%3};"
                 : "+f"(c[0]), "+f"(c[1]), "+f"(c[2]), "+f"(c[3])
                 : "r"(a[0]), "r"(a[1]), "r"(a[2]), "r"(a[3]), "r"(b0), "r"(b1));
}
__device__ __forceinline__ uint32_t pack2(__nv_bfloat16 a, __nv_bfloat16 b) {
    return (uint32_t)__bfloat16_as_ushort(a) | ((uint32_t)__bfloat16_as_ushort(b) << 16);
}
__device__ __forceinline__ void split2(float v, __nv_bfloat16& h, __nv_bfloat16& l) {
    h = __float2bfloat16(v);
    l = __float2bfloat16(v - __bfloat162float(h));
}

// ---------------- small kernels ----------------------------------------------
__global__ void k_reset() { if (threadIdx.x < NEXP) g_count[threadIdx.x] = 0; }

__global__ void k_gate(const float* __restrict__ x, const float* __restrict__ Wg,
                       const float* __restrict__ bg) {
    int t = blockIdx.x, tid = threadIdx.x;
    const float* xr = x + (size_t)t * DDIM;
    float s0 = 0.f, s1 = 0.f, s2 = 0.f, s3 = 0.f;
    for (int i = tid; i < DDIM; i += 128) {
        float xv = xr[i];
        float4 w = *reinterpret_cast<const float4*>(Wg + (size_t)i * 4);
        s0 += xv * w.x; s1 += xv * w.y; s2 += xv * w.z; s3 += xv * w.w;
    }
    #pragma unroll
    for (int o = 16; o; o >>= 1) {
        s0 += __shfl_down_sync(~0u, s0, o); s1 += __shfl_down_sync(~0u, s1, o);
        s2 += __shfl_down_sync(~0u, s2, o); s3 += __shfl_down_sync(~0u, s3, o);
    }
    __shared__ float red[4][4];
    if ((tid & 31) == 0) { int w = tid >> 5; red[w][0]=s0; red[w][1]=s1; red[w][2]=s2; red[w][3]=s3; }
    __syncthreads();
    if (tid == 0) {
        float l[4];
        #pragma unroll
        for (int e = 0; e < 4; e++) l[e] = red[0][e]+red[1][e]+red[2][e]+red[3][e]+bg[e];
        int e0 = 0;
        #pragma unroll
        for (int e = 1; e < 4; e++) if (l[e] > l[e0]) e0 = e;
        int e1 = -1;
        #pragma unroll
        for (int e = 0; e < 4; e++) { if (e == e0) continue; if (e1 < 0 || l[e] > l[e1]) e1 = e; }
        int p0 = atomicAdd(&g_count[e0], 1); g_list[e0][p0] = t * 2;
        int p1 = atomicAdd(&g_count[e1], 1); g_list[e1][p1] = t * 2 + 1;
    }
}

__global__ void k_offsets() {
    if (threadIdx.x == 0) {
        int o = 0;
        for (int e = 0; e < NEXP; e++) { g_off[e] = o; o += (g_count[e] + 127) & ~127; }
        g_off[NEXP] = o;
    }
}

__global__ void k_pack(const float* __restrict__ x) {
    int b = blockIdx.x;
    if (b >= g_off[NEXP]) return;
    int e = 0;
    #pragma unroll
    for (int i = 1; i < NEXP; i++) if (b >= g_off[i]) e = i;
    int j = b - g_off[e];
    int tid = threadIdx.x;
    __nv_bfloat16* dh = g_ahi + (size_t)b * DDIM;
    __nv_bfloat16* dl = g_alo + (size_t)b * DDIM;
    if (j < g_count[e]) {
        int slot = g_list[e][j];
        if (tid == 0) g_rowslot[b] = slot;
        const float4* src = reinterpret_cast<const float4*>(x + (size_t)(slot >> 1) * DDIM);
        float4 v0 = src[tid * 2], v1 = src[tid * 2 + 1];
        float vv[8] = {v0.x, v0.y, v0.z, v0.w, v1.x, v1.y, v1.z, v1.w};
        __nv_bfloat16 hh[8], ll[8];
        #pragma unroll
        for (int q = 0; q < 8; q++) split2(vv[q], hh[q], ll[q]);
        uint4 uh = make_uint4(pack2(hh[0],hh[1]), pack2(hh[2],hh[3]), pack2(hh[4],hh[5]), pack2(hh[6],hh[7]));
        uint4 ul = make_uint4(pack2(ll[0],ll[1]), pack2(ll[2],ll[3]), pack2(ll[4],ll[5]), pack2(ll[6],ll[7]));
        *reinterpret_cast<uint4*>(dh + tid * 8) = uh;
        *reinterpret_cast<uint4*>(dl + tid * 8) = ul;
    } else {
        if (tid == 0) g_rowslot[b] = -1;
        uint4 z = make_uint4(0, 0, 0, 0);
        *reinterpret_cast<uint4*>(dh + tid * 8) = z;
        *reinterpret_cast<uint4*>(dl + tid * 8) = z;
    }
}

// transpose + split: W [E][K][N] fp32 -> hi/lo [E][N][K] bf16
template <int K, int N>
__global__ void k_tr(const float* __restrict__ W,
                     __nv_bfloat16* __restrict__ hi, __nv_bfloat16* __restrict__ lo) {
    __shared__ float t[32][33];
    int e = blockIdx.z;
    int nb = blockIdx.x * 32, kb = blockIdx.y * 32;
    int tx = threadIdx.x, ty = threadIdx.y;
    const float* src = W + (size_t)e * K * N;
    #pragma unroll
    for (int i = 0; i < 4; i++)
        t[ty + i * 8][tx] = src[(size_t)(kb + ty + i * 8) * N + nb + tx];
    __syncthreads();
    #pragma unroll
    for (int i = 0; i < 4; i++) {
        float v = t[tx][ty + i * 8];
        size_t idx = ((size_t)e * N + nb + ty + i * 8) * K + kb + tx;
        __nv_bfloat16 h, l; split2(v, h, l);
        hi[idx] = h; lo[idx] = l;
    }
}

// ---------------- HMMA grouped GEMM ------------------------------------------
// C tile 128x128, warps 4x2 (each 32x64), K-chunk 32, 3-pass split bf16.
static constexpr int PITCH = 80;                 // smem row pitch bytes (conflict-free ldmatrix)
static constexpr int MATB  = 128 * PITCH;        // 10240 bytes: one 128x32 bf16 matrix
static constexpr int STAGE = 4 * MATB;           // Ah, Al, Bh, Bl
static constexpr int DSM   = 2 * STAGE + 512 + 16;

template <int KD, int ND, bool SWISH>
__global__ void __launch_bounds__(256, 1)
k_mma(const __nv_bfloat16* __restrict__ Ahi, const __nv_bfloat16* __restrict__ Alo,
      const __nv_bfloat16* __restrict__ Bhi, const __nv_bfloat16* __restrict__ Blo,
      const float* __restrict__ bias) {
    int row0 = blockIdx.x * 128;
    if (row0 >= g_off[NEXP]) return;
    int col0 = blockIdx.y * 128;
    int e = 0;
    #pragma unroll
    for (int i = 1; i < NEXP; i++) if (row0 >= g_off[i]) e = i;

    extern __shared__ char smc[];
    uint32_t sb = smem_u32(smc);
    float* sbias = reinterpret_cast<float*>(smc + 2 * STAGE);

    int tid = threadIdx.x, lid = tid & 31, wid = tid >> 5;
    int wm = wid >> 1, wn = wid & 1;          // warp row/col

    if (tid < 128) sbias[tid] = bias[(size_t)e * ND + col0 + tid];

    const __nv_bfloat16* Ah = Ahi + (size_t)row0 * KD;
    const __nv_bfloat16* Al = Alo + (size_t)row0 * KD;
    const __nv_bfloat16* Bh = Bhi + ((size_t)e * ND + col0) * KD;
    const __nv_bfloat16* Bl = Blo + ((size_t)e * ND + col0) * KD;

    // per-thread copy descriptors: 8 x 16B per stage
    // i = tid + t*256 ; mat = i>>10 (A/B), half = bit9 (hi/lo), r = (i>>2)&127, c = i&3
    auto copy_chunk = [&](uint32_t stage_base, int k0) {
        #pragma unroll
        for (int t = 0; t < 8; t++) {
            int i = tid + t * 256;
            int mat = i >> 10, j = i & 1023;
            int half = j >> 9, r = (j >> 2) & 127, c = j & 3;
            const __nv_bfloat16* src =
                (mat ? (half ? Bl : Bh) : (half ? Al : Ah)) + (size_t)r * KD + k0 + c * 8;
            uint32_t dst = stage_base + mat * (2 * MATB) + half * MATB + r * PITCH + c * 16;
            CP_ASYNC16(dst, src);
        }
    };

    float acc[2][8][4];
    #pragma unroll
    for (int a = 0; a < 2; a++)
        #pragma unroll
        for (int b = 0; b < 8; b++)
            #pragma unroll
            for (int q = 0; q < 4; q++) acc[a][b][q] = 0.f;

    const int NCH = KD / 32;
    copy_chunk(sb, 0); CP_COMMIT();
    copy_chunk(sb + STAGE, 32); CP_COMMIT();

    uint32_t lane_off = (uint32_t)((lid & 15) * PITCH + (lid >> 4) * 16);

    for (int cch = 0; cch < NCH; cch++) {
        if (cch + 1 < NCH) { CP_WAIT1(); } else { CP_WAIT0(); }
        __syncthreads();
        uint32_t st = sb + (cch & 1) * STAGE;
        #pragma unroll
        for (int p = 0; p < 3; p++) {
            uint32_t Ab = st + (p == 2 ? MATB : 0);                 // p0,p1: Ah ; p2: Al
            uint32_t Bb = st + 2 * MATB + (p == 1 ? MATB : 0);      // p0,p2: Bh ; p1: Bl
            #pragma unroll
            for (int kt = 0; kt < 2; kt++) {
                uint32_t afr[2][4];
                #pragma unroll
                for (int mi = 0; mi < 2; mi++)
                    ldm_x4(afr[mi], Ab + (wm * 32 + mi * 16) * PITCH + kt * 32 + lane_off);
                #pragma unroll
                for (int pr = 0; pr < 4; pr++) {
                    uint32_t bfr[4];
                    ldm_x4(bfr, Bb + (wn * 64 + pr * 16) * PITCH + kt * 32 + lane_off);
                    #pragma unroll
                    for (int mi = 0; mi < 2; mi++) {
                        mma16816(acc[mi][pr * 2],     afr[mi], bfr[0], bfr[2]);
                        mma16816(acc[mi][pr * 2 + 1], afr[mi], bfr[1], bfr[3]);
                    }
                }
            }
        }
        __syncthreads();
        if (cch + 2 < NCH) { copy_chunk(sb + (cch & 1) * STAGE, (cch + 2) * 32); CP_COMMIT(); }
    }

    // ---- epilogue ----
    #pragma unroll
    for (int mi = 0; mi < 2; mi++) {
        #pragma unroll
        for (int ni = 0; ni < 8; ni++) {
            int ccol = wn * 64 + ni * 8 + (lid & 3) * 2;
            #pragma unroll
            for (int h = 0; h < 2; h++) {          // h=0: c0,c1 ; h=1: c2,c3 (row+8)
                int lrow = wm * 32 + mi * 16 + (lid >> 2) + h * 8;
                int grow = row0 + lrow;
                float v0 = acc[mi][ni][h * 2]     + sbias[ccol];
                float v1 = acc[mi][ni][h * 2 + 1] + sbias[ccol + 1];
                if (SWISH) {
                    v0 = v0 / (1.0f + expf(-v0));
                    v1 = v1 / (1.0f + expf(-v1));
                    __nv_bfloat16 h0, l0, h1, l1;
                    split2(v0, h0, l0); split2(v1, h1, l1);
                    size_t idx = (size_t)grow * ND + col0 + ccol;
                    *reinterpret_cast<uint32_t*>(g_hhi + idx) = pack2(h0, h1);
                    *reinterpret_cast<uint32_t*>(g_hlo + idx) = pack2(l0, l1);
                } else {
                    int slot = g_rowslot[grow];
                    if (slot >= 0) {
                        float* yp = g_y + (size_t)slot * DDIM + col0 + ccol;
                        yp[0] = v0; yp[1] = v1;
                    }
                }
            }
        }
    }
}

// out[t] = y[2t] + y[2t+1]
__global__ void k_combine(float* __restrict__ out) {
    int i = blockIdx.x * blockDim.x + threadIdx.x;
    if (i >= NTOK * DDIM / 4) return;
    int t = i >> 8, d = i & 255;
    const float4* y = reinterpret_cast<const float4*>(g_y);
    float4 a = y[(size_t)(2 * t) * 256 + d];
    float4 b = y[(size_t)(2 * t + 1) * 256 + d];
    reinterpret_cast<float4*>(out)[i] = make_float4(a.x + b.x, a.y + b.y, a.z + b.z, a.w + b.w);
}

// -----------------------------------------------------------------------------
extern "C" void kernel_launch(void* const* d_in, const int* in_sizes, int n_in,
                              void* d_out, int out_size) {
    const float* x  = (const float*)d_in[0];
    const float* Wg = (const float*)d_in[1];
    const float* bg = (const float*)d_in[2];
    const float* W1 = (const float*)d_in[3];
    const float* b1 = (const float*)d_in[4];
    const float* W2 = (const float*)d_in[5];
    const float* b2 = (const float*)d_in[6];
    float* out = (float*)d_out;

    __nv_bfloat16 *ahi, *alo, *hhi, *hlo, *w1hi, *w1lo, *w2hi, *w2lo;
    cudaGetSymbolAddress((void**)&ahi, g_ahi);   cudaGetSymbolAddress((void**)&alo, g_alo);
    cudaGetSymbolAddress((void**)&hhi, g_hhi);   cudaGetSymbolAddress((void**)&hlo, g_hlo);
    cudaGetSymbolAddress((void**)&w1hi, g_w1hi); cudaGetSymbolAddress((void**)&w1lo, g_w1lo);
    cudaGetSymbolAddress((void**)&w2hi, g_w2hi); cudaGetSymbolAddress((void**)&w2lo, g_w2lo);

    cudaFuncSetAttribute(k_mma<DDIM, FDIM, true>,  cudaFuncAttributeMaxDynamicSharedMemorySize, DSM);
    cudaFuncSetAttribute(k_mma<FDIM, DDIM, false>, cudaFuncAttributeMaxDynamicSharedMemorySize, DSM);

    k_reset<<<1, 32>>>();
    k_gate<<<NTOK, 128>>>(x, Wg, bg);
    k_offsets<<<1, 32>>>();
    k_pack<<<RPAD, 128>>>(x);
    k_tr<DDIM, FDIM><<<dim3(FDIM / 32, DDIM / 32, NEXP), dim3(32, 8)>>>(W1, w1hi, w1lo);
    k_tr<FDIM, DDIM><<<dim3(DDIM / 32, FDIM / 32, NEXP), dim3(32, 8)>>>(W2, w2hi, w2lo);

    dim3 g1(RPAD / 128, FDIM / 128);   // (132, 32)
    k_mma<DDIM, FDIM, true><<<g1, 256, DSM>>>(ahi, alo, w1hi, w1lo, b1);
    dim3 g2(RPAD / 128, DDIM / 128);   // (132, 8)
    k_mma<FDIM, DDIM, false><<<g2, 256, DSM>>>(hhi, hlo, w2hi, w2lo, b2);

    int nvec = NTOK * DDIM / 4;
    k_combine<<<(nvec + 255) / 256, 256>>>(out);
}

// round 5
// speedup vs baseline: 3.2552x; 1.6523x over previous
#include <cuda_runtime.h>
#include <cuda_fp16.h>
#include <cstdint>
#include <cmath>

#define NTOK 8192       // B*S
#define DDIM 1024
#define FDIM 4096
#define NEXP 4
#define NSLOT (NTOK * 2)
#define RPAD (NSLOT + 128 * NEXP)   // 16896

// ---------------- device scratch (module-load; no runtime alloc) ------------
__device__ int g_count[NEXP];
__device__ int g_list[NEXP][NTOK];
__device__ int g_off[NEXP + 1];
__device__ int g_rowslot[RPAD];
__device__ __half g_ahi[(size_t)RPAD * DDIM];
__device__ __half g_alo[(size_t)RPAD * DDIM];
__device__ __half g_hhi[(size_t)RPAD * FDIM];
__device__ __half g_hlo[(size_t)RPAD * FDIM];
__device__ __half g_w1[(size_t)NEXP * FDIM * DDIM];   // [E][F][D] fp16(W1^T)
__device__ __half g_w2[(size_t)NEXP * DDIM * FDIM];   // [E][D][F] fp16(W2^T)
__device__ float g_y[(size_t)NSLOT * DDIM];

// ---------------- helpers ----------------------------------------------------
__device__ __forceinline__ uint32_t smem_u32(const void* p) {
    uint32_t a;
    asm("{ .reg .u64 t; cvta.to.shared.u64 t, %1; cvt.u32.u64 %0, t; }" : "=r"(a) : "l"(p));
    return a;
}
#define CP_ASYNC16(dst, src) \
    asm volatile("cp.async.cg.shared.global [%0], [%1], 16;" :: "r"(dst), "l"(src))
#define CP_COMMIT() asm volatile("cp.async.commit_group;" ::: "memory")
#define CP_WAIT1()  asm volatile("cp.async.wait_group 1;" ::: "memory")
#define CP_WAIT0()  asm volatile("cp.async.wait_group 0;" ::: "memory")

__device__ __forceinline__ void ldm_x4(uint32_t* r, uint32_t addr) {
    asm volatile("ldmatrix.sync.aligned.m8n8.x4.shared.b16 {%0,%1,%2,%3}, [%4];"
                 : "=r"(r[0]), "=r"(r[1]), "=r"(r[2]), "=r"(r[3]) : "r"(addr));
}
__device__ __forceinline__ void mma16816(float* c, const uint32_t* a, uint32_t b0, uint32_t b1) {
    asm volatile("mma.sync.aligned.m16n8k16.row.col.f32.f16.f16.f32 "
                 "{%0,%1,%2,%3}, {%4,%5,%6,%7}, {%8,%9}, {%0,%1,%2,%3};"
                 : "+f"(c[0]), "+f"(c[1]), "+f"(c[2]), "+f"(c[3])
                 : "r"(a[0]), "r"(a[1]), "r"(a[2]), "r"(a[3]), "r"(b0), "r"(b1));
}
__device__ __forceinline__ uint32_t pack2h(__half a, __half b) {
    return (uint32_t)__half_as_ushort(a) | ((uint32_t)__half_as_ushort(b) << 16);
}
__device__ __forceinline__ void split2h(float v, __half& h, __half& l) {
    h = __float2half(v);
    l = __float2half(v - __half2float(h));
}

// ---------------- small kernels ----------------------------------------------
__global__ void k_reset() { if (threadIdx.x < NEXP) g_count[threadIdx.x] = 0; }

__global__ void k_gate(const float* __restrict__ x, const float* __restrict__ Wg,
                       const float* __restrict__ bg) {
    int t = blockIdx.x, tid = threadIdx.x;
    const float* xr = x + (size_t)t * DDIM;
    float s0 = 0.f, s1 = 0.f, s2 = 0.f, s3 = 0.f;
    for (int i = tid; i < DDIM; i += 128) {
        float xv = xr[i];
        float4 w = *reinterpret_cast<const float4*>(Wg + (size_t)i * 4);
        s0 += xv * w.x; s1 += xv * w.y; s2 += xv * w.z; s3 += xv * w.w;
    }
    #pragma unroll
    for (int o = 16; o; o >>= 1) {
        s0 += __shfl_down_sync(~0u, s0, o); s1 += __shfl_down_sync(~0u, s1, o);
        s2 += __shfl_down_sync(~0u, s2, o); s3 += __shfl_down_sync(~0u, s3, o);
    }
    __shared__ float red[4][4];
    if ((tid & 31) == 0) { int w = tid >> 5; red[w][0]=s0; red[w][1]=s1; red[w][2]=s2; red[w][3]=s3; }
    __syncthreads();
    if (tid == 0) {
        float l[4];
        #pragma unroll
        for (int e = 0; e < 4; e++) l[e] = red[0][e]+red[1][e]+red[2][e]+red[3][e]+bg[e];
        int e0 = 0;
        #pragma unroll
        for (int e = 1; e < 4; e++) if (l[e] > l[e0]) e0 = e;
        int e1 = -1;
        #pragma unroll
        for (int e = 0; e < 4; e++) { if (e == e0) continue; if (e1 < 0 || l[e] > l[e1]) e1 = e; }
        int p0 = atomicAdd(&g_count[e0], 1); g_list[e0][p0] = t * 2;
        int p1 = atomicAdd(&g_count[e1], 1); g_list[e1][p1] = t * 2 + 1;
    }
}

__global__ void k_offsets() {
    if (threadIdx.x == 0) {
        int o = 0;
        for (int e = 0; e < NEXP; e++) { g_off[e] = o; o += (g_count[e] + 127) & ~127; }
        g_off[NEXP] = o;
    }
}

__global__ void k_pack(const float* __restrict__ x) {
    int b = blockIdx.x;
    if (b >= g_off[NEXP]) return;
    int e = 0;
    #pragma unroll
    for (int i = 1; i < NEXP; i++) if (b >= g_off[i]) e = i;
    int j = b - g_off[e];
    int tid = threadIdx.x;
    __half* dh = g_ahi + (size_t)b * DDIM;
    __half* dl = g_alo + (size_t)b * DDIM;
    if (j < g_count[e]) {
        int slot = g_list[e][j];
        if (tid == 0) g_rowslot[b] = slot;
        const float4* src = reinterpret_cast<const float4*>(x + (size_t)(slot >> 1) * DDIM);
        float4 v0 = src[tid * 2], v1 = src[tid * 2 + 1];
        float vv[8] = {v0.x, v0.y, v0.z, v0.w, v1.x, v1.y, v1.z, v1.w};
        __half hh[8], ll[8];
        #pragma unroll
        for (int q = 0; q < 8; q++) split2h(vv[q], hh[q], ll[q]);
        uint4 uh = make_uint4(pack2h(hh[0],hh[1]), pack2h(hh[2],hh[3]), pack2h(hh[4],hh[5]), pack2h(hh[6],hh[7]));
        uint4 ul = make_uint4(pack2h(ll[0],ll[1]), pack2h(ll[2],ll[3]), pack2h(ll[4],ll[5]), pack2h(ll[6],ll[7]));
        *reinterpret_cast<uint4*>(dh + tid * 8) = uh;
        *reinterpret_cast<uint4*>(dl + tid * 8) = ul;
    } else {
        if (tid == 0) g_rowslot[b] = -1;
        uint4 z = make_uint4(0, 0, 0, 0);
        *reinterpret_cast<uint4*>(dh + tid * 8) = z;
        *reinterpret_cast<uint4*>(dl + tid * 8) = z;
    }
}

// transpose: W [E][K][N] fp32 -> fp16 [E][N][K]
template <int K, int N>
__global__ void k_tr(const float* __restrict__ W, __half* __restrict__ hi) {
    __shared__ float t[32][33];
    int e = blockIdx.z;
    int nb = blockIdx.x * 32, kb = blockIdx.y * 32;
    int tx = threadIdx.x, ty = threadIdx.y;
    const float* src = W + (size_t)e * K * N;
    #pragma unroll
    for (int i = 0; i < 4; i++)
        t[ty + i * 8][tx] = src[(size_t)(kb + ty + i * 8) * N + nb + tx];
    __syncthreads();
    #pragma unroll
    for (int i = 0; i < 4; i++) {
        float v = t[tx][ty + i * 8];
        size_t idx = ((size_t)e * N + nb + ty + i * 8) * K + kb + tx;
        hi[idx] = __float2half(v);
    }
}

// ---------------- HMMA grouped GEMM (fp16 2-pass A-split) --------------------
// C tile 128x128, warps 4x2 (each 32x64), K-chunk 32.
// smem per stage: Ah | Al | Bh  (each 128x32 fp16, pitch 80B)
static constexpr int PITCH = 80;
static constexpr int MATB  = 128 * PITCH;        // 10240
static constexpr int STAGE = 3 * MATB;           // 30720
static constexpr int DSM   = 2 * STAGE + 512 + 16;

template <int KD, int ND, bool SWISH>
__global__ void __launch_bounds__(256, 1)
k_mma(const __half* __restrict__ Ahi, const __half* __restrict__ Alo,
      const __half* __restrict__ Bhw, const float* __restrict__ bias) {
    int row0 = blockIdx.x * 128;
    if (row0 >= g_off[NEXP]) return;
    int col0 = blockIdx.y * 128;
    int e = 0;
    #pragma unroll
    for (int i = 1; i < NEXP; i++) if (row0 >= g_off[i]) e = i;

    extern __shared__ char smc[];
    uint32_t sb = smem_u32(smc);
    float* sbias = reinterpret_cast<float*>(smc + 2 * STAGE);

    int tid = threadIdx.x, lid = tid & 31, wid = tid >> 5;
    int wm = wid >> 1, wn = wid & 1;

    if (tid < 128) sbias[tid] = bias[(size_t)e * ND + col0 + tid];

    const __half* Ah = Ahi + (size_t)row0 * KD;
    const __half* Al = Alo + (size_t)row0 * KD;
    const __half* Bh = Bhw + ((size_t)e * ND + col0) * KD;

    // copy: 3 mats x 128 rows x 2 x 16B = 1536 cp.async / 256 thr = 6 each
    auto copy_chunk = [&](uint32_t stage_base, int k0) {
        #pragma unroll
        for (int t = 0; t < 6; t++) {
            int i = tid + t * 256;
            int mat = i >> 9, j = i & 511;
            int r = j >> 2, c = j & 3;
            const __half* src = (mat == 0 ? Ah : (mat == 1 ? Al : Bh)) + (size_t)r * KD + k0 + c * 8;
            uint32_t dst = stage_base + mat * MATB + r * PITCH + c * 16;
            CP_ASYNC16(dst, src);
        }
    };

    float acc[2][8][4];
    #pragma unroll
    for (int a = 0; a < 2; a++)
        #pragma unroll
        for (int b = 0; b < 8; b++)
            #pragma unroll
            for (int q = 0; q < 4; q++) acc[a][b][q] = 0.f;

    const int NCH = KD / 32;
    copy_chunk(sb, 0); CP_COMMIT();
    copy_chunk(sb + STAGE, 32); CP_COMMIT();

    uint32_t lane_off = (uint32_t)((lid & 15) * PITCH + (lid >> 4) * 16);

    for (int cch = 0; cch < NCH; cch++) {
        if (cch + 1 < NCH) { CP_WAIT1(); } else { CP_WAIT0(); }
        __syncthreads();
        uint32_t st = sb + (cch & 1) * STAGE;
        #pragma unroll
        for (int kt = 0; kt < 2; kt++) {
            uint32_t ah[2][4], al[2][4];
            #pragma unroll
            for (int mi = 0; mi < 2; mi++) {
                ldm_x4(ah[mi], st +        (wm * 32 + mi * 16) * PITCH + kt * 32 + lane_off);
                ldm_x4(al[mi], st + MATB + (wm * 32 + mi * 16) * PITCH + kt * 32 + lane_off);
            }
            #pragma unroll
            for (int pr = 0; pr < 4; pr++) {
                uint32_t bfr[4];
                ldm_x4(bfr, st + 2 * MATB + (wn * 64 + pr * 16) * PITCH + kt * 32 + lane_off);
                #pragma unroll
                for (int mi = 0; mi < 2; mi++) {
                    mma16816(acc[mi][pr * 2],     ah[mi], bfr[0], bfr[2]);
                    mma16816(acc[mi][pr * 2 + 1], ah[mi], bfr[1], bfr[3]);
                    mma16816(acc[mi][pr * 2],     al[mi], bfr[0], bfr[2]);
                    mma16816(acc[mi][pr * 2 + 1], al[mi], bfr[1], bfr[3]);
                }
            }
        }
        __syncthreads();
        if (cch + 2 < NCH) { copy_chunk(sb + (cch & 1) * STAGE, (cch + 2) * 32); CP_COMMIT(); }
    }

    // ---- epilogue ----
    #pragma unroll
    for (int mi = 0; mi < 2; mi++) {
        #pragma unroll
        for (int ni = 0; ni < 8; ni++) {
            int ccol = wn * 64 + ni * 8 + (lid & 3) * 2;
            #pragma unroll
            for (int h = 0; h < 2; h++) {
                int lrow = wm * 32 + mi * 16 + (lid >> 2) + h * 8;
                int grow = row0 + lrow;
                float v0 = acc[mi][ni][h * 2]     + sbias[ccol];
                float v1 = acc[mi][ni][h * 2 + 1] + sbias[ccol + 1];
                if (SWISH) {
                    v0 = v0 / (1.0f + expf(-v0));
                    v1 = v1 / (1.0f + expf(-v1));
                    __half h0, l0, h1, l1;
                    split2h(v0, h0, l0); split2h(v1, h1, l1);
                    size_t idx = (size_t)grow * ND + col0 + ccol;
                    *reinterpret_cast<uint32_t*>(g_hhi + idx) = pack2h(h0, h1);
                    *reinterpret_cast<uint32_t*>(g_hlo + idx) = pack2h(l0, l1);
                } else {
                    int slot = g_rowslot[grow];
                    if (slot >= 0) {
                        float* yp = g_y + (size_t)slot * DDIM + col0 + ccol;
                        yp[0] = v0; yp[1] = v1;
                    }
                }
            }
        }
    }
}

// out[t] = y[2t] + y[2t+1]
__global__ void k_combine(float* __restrict__ out) {
    int i = blockIdx.x * blockDim.x + threadIdx.x;
    if (i >= NTOK * DDIM / 4) return;
    int t = i >> 8, d = i & 255;
    const float4* y = reinterpret_cast<const float4*>(g_y);
    float4 a = y[(size_t)(2 * t) * 256 + d];
    float4 b = y[(size_t)(2 * t + 1) * 256 + d];
    reinterpret_cast<float4*>(out)[i] = make_float4(a.x + b.x, a.y + b.y, a.z + b.z, a.w + b.w);
}

// -----------------------------------------------------------------------------
extern "C" void kernel_launch(void* const* d_in, const int* in_sizes, int n_in,
                              void* d_out, int out_size) {
    const float* x  = (const float*)d_in[0];
    const float* Wg = (const float*)d_in[1];
    const float* bg = (const float*)d_in[2];
    const float* W1 = (const float*)d_in[3];
    const float* b1 = (const float*)d_in[4];
    const float* W2 = (const float*)d_in[5];
    const float* b2 = (const float*)d_in[6];
    float* out = (float*)d_out;

    __half *ahi, *alo, *hhi, *hlo, *w1p, *w2p;
    cudaGetSymbolAddress((void**)&ahi, g_ahi); cudaGetSymbolAddress((void**)&alo, g_alo);
    cudaGetSymbolAddress((void**)&hhi, g_hhi); cudaGetSymbolAddress((void**)&hlo, g_hlo);
    cudaGetSymbolAddress((void**)&w1p, g_w1);  cudaGetSymbolAddress((void**)&w2p, g_w2);

    cudaFuncSetAttribute(k_mma<DDIM, FDIM, true>,  cudaFuncAttributeMaxDynamicSharedMemorySize, DSM);
    cudaFuncSetAttribute(k_mma<FDIM, DDIM, false>, cudaFuncAttributeMaxDynamicSharedMemorySize, DSM);

    k_reset<<<1, 32>>>();
    k_gate<<<NTOK, 128>>>(x, Wg, bg);
    k_offsets<<<1, 32>>>();
    k_pack<<<RPAD, 128>>>(x);
    k_tr<DDIM, FDIM><<<dim3(FDIM / 32, DDIM / 32, NEXP), dim3(32, 8)>>>(W1, w1p);
    k_tr<FDIM, DDIM><<<dim3(DDIM / 32, FDIM / 32, NEXP), dim3(32, 8)>>>(W2, w2p);

    dim3 g1(RPAD / 128, FDIM / 128);   // (132, 32)
    k_mma<DDIM, FDIM, true><<<g1, 256, DSM>>>(ahi, alo, w1p, b1);
    dim3 g2(RPAD / 128, DDIM / 128);   // (132, 8)
    k_mma<FDIM, DDIM, false><<<g2, 256, DSM>>>(hhi, hlo, w2p, b2);

    int nvec = NTOK * DDIM / 4;
    k_combine<<<(nvec + 255) / 256, 256>>>(out);
}

// round 6
// speedup vs baseline: 4.1261x; 1.2675x over previous
#include <cuda_runtime.h>
#include <cuda_fp16.h>
#include <cstdint>
#include <cmath>

#define NTOK 8192       // B*S
#define DDIM 1024
#define FDIM 4096
#define NEXP 4
#define NSLOT (NTOK * 2)
#define RPAD (NSLOT + 128 * NEXP)   // 16896

// ---------------- device scratch (module-load; no runtime alloc) ------------
__device__ int g_count[NEXP];
__device__ int g_list[NEXP][NTOK];
__device__ int g_off[NEXP + 1];
__device__ int g_rowslot[RPAD];
__device__ __half g_ahi[(size_t)RPAD * DDIM];
__device__ __half g_alo[(size_t)RPAD * DDIM];
__device__ __half g_h[(size_t)RPAD * FDIM];           // h as fp16 (single)
__device__ __half g_w1[(size_t)NEXP * FDIM * DDIM];   // [E][F][D] fp16(W1^T)
__device__ __half g_w2[(size_t)NEXP * DDIM * FDIM];   // [E][D][F] fp16(W2^T)
__device__ float g_y[(size_t)NSLOT * DDIM];

// ---------------- helpers ----------------------------------------------------
__device__ __forceinline__ uint32_t smem_u32(const void* p) {
    uint32_t a;
    asm("{ .reg .u64 t; cvta.to.shared.u64 t, %1; cvt.u32.u64 %0, t; }" : "=r"(a) : "l"(p));
    return a;
}
#define CP_ASYNC16(dst, src) \
    asm volatile("cp.async.cg.shared.global [%0], [%1], 16;" :: "r"(dst), "l"(src))
#define CP_COMMIT() asm volatile("cp.async.commit_group;" ::: "memory")
#define CP_WAIT1()  asm volatile("cp.async.wait_group 1;" ::: "memory")
#define CP_WAIT0()  asm volatile("cp.async.wait_group 0;" ::: "memory")

__device__ __forceinline__ void ldm_x4(uint32_t* r, uint32_t addr) {
    asm volatile("ldmatrix.sync.aligned.m8n8.x4.shared.b16 {%0,%1,%2,%3}, [%4];"
                 : "=r"(r[0]), "=r"(r[1]), "=r"(r[2]), "=r"(r[3]) : "r"(addr));
}
__device__ __forceinline__ void mma16816(float* c, const uint32_t* a, uint32_t b0, uint32_t b1) {
    asm volatile("mma.sync.aligned.m16n8k16.row.col.f32.f16.f16.f32 "
                 "{%0,%1,%2,%3}, {%4,%5,%6,%7}, {%8,%9}, {%0,%1,%2,%3};"
                 : "+f"(c[0]), "+f"(c[1]), "+f"(c[2]), "+f"(c[3])
                 : "r"(a[0]), "r"(a[1]), "r"(a[2]), "r"(a[3]), "r"(b0), "r"(b1));
}
__device__ __forceinline__ uint32_t pack2h(__half a, __half b) {
    return (uint32_t)__half_as_ushort(a) | ((uint32_t)__half_as_ushort(b) << 16);
}
__device__ __forceinline__ void split2h(float v, __half& h, __half& l) {
    h = __float2half(v);
    l = __float2half(v - __half2float(h));
}

// ---------------- small kernels ----------------------------------------------
__global__ void k_reset() { if (threadIdx.x < NEXP) g_count[threadIdx.x] = 0; }

__global__ void k_gate(const float* __restrict__ x, const float* __restrict__ Wg,
                       const float* __restrict__ bg) {
    int t = blockIdx.x, tid = threadIdx.x;
    const float* xr = x + (size_t)t * DDIM;
    float s0 = 0.f, s1 = 0.f, s2 = 0.f, s3 = 0.f;
    for (int i = tid; i < DDIM; i += 128) {
        float xv = xr[i];
        float4 w = *reinterpret_cast<const float4*>(Wg + (size_t)i * 4);
        s0 += xv * w.x; s1 += xv * w.y; s2 += xv * w.z; s3 += xv * w.w;
    }
    #pragma unroll
    for (int o = 16; o; o >>= 1) {
        s0 += __shfl_down_sync(~0u, s0, o); s1 += __shfl_down_sync(~0u, s1, o);
        s2 += __shfl_down_sync(~0u, s2, o); s3 += __shfl_down_sync(~0u, s3, o);
    }
    __shared__ float red[4][4];
    if ((tid & 31) == 0) { int w = tid >> 5; red[w][0]=s0; red[w][1]=s1; red[w][2]=s2; red[w][3]=s3; }
    __syncthreads();
    if (tid == 0) {
        float l[4];
        #pragma unroll
        for (int e = 0; e < 4; e++) l[e] = red[0][e]+red[1][e]+red[2][e]+red[3][e]+bg[e];
        int e0 = 0;
        #pragma unroll
        for (int e = 1; e < 4; e++) if (l[e] > l[e0]) e0 = e;
        int e1 = -1;
        #pragma unroll
        for (int e = 0; e < 4; e++) { if (e == e0) continue; if (e1 < 0 || l[e] > l[e1]) e1 = e; }
        int p0 = atomicAdd(&g_count[e0], 1); g_list[e0][p0] = t * 2;
        int p1 = atomicAdd(&g_count[e1], 1); g_list[e1][p1] = t * 2 + 1;
    }
}

__global__ void k_offsets() {
    if (threadIdx.x == 0) {
        int o = 0;
        for (int e = 0; e < NEXP; e++) { g_off[e] = o; o += (g_count[e] + 127) & ~127; }
        g_off[NEXP] = o;
    }
}

__global__ void k_pack(const float* __restrict__ x) {
    int b = blockIdx.x;
    if (b >= g_off[NEXP]) return;
    int e = 0;
    #pragma unroll
    for (int i = 1; i < NEXP; i++) if (b >= g_off[i]) e = i;
    int j = b - g_off[e];
    int tid = threadIdx.x;
    __half* dh = g_ahi + (size_t)b * DDIM;
    __half* dl = g_alo + (size_t)b * DDIM;
    if (j < g_count[e]) {
        int slot = g_list[e][j];
        if (tid == 0) g_rowslot[b] = slot;
        const float4* src = reinterpret_cast<const float4*>(x + (size_t)(slot >> 1) * DDIM);
        float4 v0 = src[tid * 2], v1 = src[tid * 2 + 1];
        float vv[8] = {v0.x, v0.y, v0.z, v0.w, v1.x, v1.y, v1.z, v1.w};
        __half hh[8], ll[8];
        #pragma unroll
        for (int q = 0; q < 8; q++) split2h(vv[q], hh[q], ll[q]);
        uint4 uh = make_uint4(pack2h(hh[0],hh[1]), pack2h(hh[2],hh[3]), pack2h(hh[4],hh[5]), pack2h(hh[6],hh[7]));
        uint4 ul = make_uint4(pack2h(ll[0],ll[1]), pack2h(ll[2],ll[3]), pack2h(ll[4],ll[5]), pack2h(ll[6],ll[7]));
        *reinterpret_cast<uint4*>(dh + tid * 8) = uh;
        *reinterpret_cast<uint4*>(dl + tid * 8) = ul;
    } else {
        if (tid == 0) g_rowslot[b] = -1;
        uint4 z = make_uint4(0, 0, 0, 0);
        *reinterpret_cast<uint4*>(dh + tid * 8) = z;
        *reinterpret_cast<uint4*>(dl + tid * 8) = z;
    }
}

// transpose: W [E][K][N] fp32 -> fp16 [E][N][K]
template <int K, int N>
__global__ void k_tr(const float* __restrict__ W, __half* __restrict__ hi) {
    __shared__ float t[32][33];
    int e = blockIdx.z;
    int nb = blockIdx.x * 32, kb = blockIdx.y * 32;
    int tx = threadIdx.x, ty = threadIdx.y;
    const float* src = W + (size_t)e * K * N;
    #pragma unroll
    for (int i = 0; i < 4; i++)
        t[ty + i * 8][tx] = src[(size_t)(kb + ty + i * 8) * N + nb + tx];
    __syncthreads();
    #pragma unroll
    for (int i = 0; i < 4; i++) {
        float v = t[tx][ty + i * 8];
        size_t idx = ((size_t)e * N + nb + ty + i * 8) * K + kb + tx;
        hi[idx] = __float2half(v);
    }
}

// ---------------- HMMA grouped GEMM ------------------------------------------
// C tile 128x128, warps 4x2 (each 32x64), K-chunk 32.
// TWOPASS: smem stage = Ah | Al | B ; else Ah | B.
static constexpr int PITCH = 80;
static constexpr int MATB  = 128 * PITCH;        // 10240

template <int KD, int ND, bool SWISH, bool TWOPASS>
__global__ void __launch_bounds__(256, 1)
k_mma(const __half* __restrict__ Ahi, const __half* __restrict__ Alo,
      const __half* __restrict__ Bhw, const float* __restrict__ bias) {
    constexpr int NMAT  = TWOPASS ? 3 : 2;
    constexpr int STAGE = NMAT * MATB;
    int row0 = blockIdx.x * 128;
    if (row0 >= g_off[NEXP]) return;
    int col0 = blockIdx.y * 128;
    int e = 0;
    #pragma unroll
    for (int i = 1; i < NEXP; i++) if (row0 >= g_off[i]) e = i;

    extern __shared__ char smc[];
    uint32_t sb = smem_u32(smc);
    float* sbias = reinterpret_cast<float*>(smc + 2 * STAGE);

    int tid = threadIdx.x, lid = tid & 31, wid = tid >> 5;
    int wm = wid >> 1, wn = wid & 1;

    if (tid < 128) sbias[tid] = bias[(size_t)e * ND + col0 + tid];

    const __half* Ah = Ahi + (size_t)row0 * KD;
    const __half* Al = TWOPASS ? (Alo + (size_t)row0 * KD) : nullptr;
    const __half* Bh = Bhw + ((size_t)e * ND + col0) * KD;

    auto copy_chunk = [&](uint32_t stage_base, int k0) {
        #pragma unroll
        for (int t = 0; t < NMAT * 2; t++) {
            int i = tid + t * 256;
            int mat = i >> 9, j = i & 511;
            int r = j >> 2, c = j & 3;
            const __half* src;
            if (TWOPASS) src = (mat == 0 ? Ah : (mat == 1 ? Al : Bh)) + (size_t)r * KD + k0 + c * 8;
            else         src = (mat == 0 ? Ah : Bh) + (size_t)r * KD + k0 + c * 8;
            uint32_t dst = stage_base + mat * MATB + r * PITCH + c * 16;
            CP_ASYNC16(dst, src);
        }
    };

    float acc[2][8][4];
    #pragma unroll
    for (int a = 0; a < 2; a++)
        #pragma unroll
        for (int b = 0; b < 8; b++)
            #pragma unroll
            for (int q = 0; q < 4; q++) acc[a][b][q] = 0.f;

    const int NCH = KD / 32;
    copy_chunk(sb, 0); CP_COMMIT();
    copy_chunk(sb + STAGE, 32); CP_COMMIT();

    uint32_t lane_off = (uint32_t)((lid & 15) * PITCH + (lid >> 4) * 16);
    const uint32_t boff = (NMAT - 1) * MATB;

    for (int cch = 0; cch < NCH; cch++) {
        if (cch + 1 < NCH) { CP_WAIT1(); } else { CP_WAIT0(); }
        __syncthreads();
        uint32_t st = sb + (cch & 1) * STAGE;
        #pragma unroll
        for (int kt = 0; kt < 2; kt++) {
            uint32_t ah[2][4], al[2][4];
            #pragma unroll
            for (int mi = 0; mi < 2; mi++) {
                ldm_x4(ah[mi], st + (wm * 32 + mi * 16) * PITCH + kt * 32 + lane_off);
                if (TWOPASS)
                    ldm_x4(al[mi], st + MATB + (wm * 32 + mi * 16) * PITCH + kt * 32 + lane_off);
            }
            #pragma unroll
            for (int pr = 0; pr < 4; pr++) {
                uint32_t bfr[4];
                ldm_x4(bfr, st + boff + (wn * 64 + pr * 16) * PITCH + kt * 32 + lane_off);
                #pragma unroll
                for (int mi = 0; mi < 2; mi++) {
                    mma16816(acc[mi][pr * 2],     ah[mi], bfr[0], bfr[2]);
                    mma16816(acc[mi][pr * 2 + 1], ah[mi], bfr[1], bfr[3]);
                    if (TWOPASS) {
                        mma16816(acc[mi][pr * 2],     al[mi], bfr[0], bfr[2]);
                        mma16816(acc[mi][pr * 2 + 1], al[mi], bfr[1], bfr[3]);
                    }
                }
            }
        }
        __syncthreads();
        if (cch + 2 < NCH) { copy_chunk(sb + (cch & 1) * STAGE, (cch + 2) * 32); CP_COMMIT(); }
    }

    // ---- epilogue ----
    #pragma unroll
    for (int mi = 0; mi < 2; mi++) {
        #pragma unroll
        for (int ni = 0; ni < 8; ni++) {
            int ccol = wn * 64 + ni * 8 + (lid & 3) * 2;
            #pragma unroll
            for (int h = 0; h < 2; h++) {
                int lrow = wm * 32 + mi * 16 + (lid >> 2) + h * 8;
                int grow = row0 + lrow;
                float v0 = acc[mi][ni][h * 2]     + sbias[ccol];
                float v1 = acc[mi][ni][h * 2 + 1] + sbias[ccol + 1];
                if (SWISH) {
                    v0 = v0 / (1.0f + expf(-v0));
                    v1 = v1 / (1.0f + expf(-v1));
                    size_t idx = (size_t)grow * ND + col0 + ccol;
                    *reinterpret_cast<uint32_t*>(g_h + idx) =
                        pack2h(__float2half(v0), __float2half(v1));
                } else {
                    int slot = g_rowslot[grow];
                    if (slot >= 0) {
                        float* yp = g_y + (size_t)slot * DDIM + col0 + ccol;
                        yp[0] = v0; yp[1] = v1;
                    }
                }
            }
        }
    }
}

// out[t] = y[2t] + y[2t+1]
__global__ void k_combine(float* __restrict__ out) {
    int i = blockIdx.x * blockDim.x + threadIdx.x;
    if (i >= NTOK * DDIM / 4) return;
    int t = i >> 8, d = i & 255;
    const float4* y = reinterpret_cast<const float4*>(g_y);
    float4 a = y[(size_t)(2 * t) * 256 + d];
    float4 b = y[(size_t)(2 * t + 1) * 256 + d];
    reinterpret_cast<float4*>(out)[i] = make_float4(a.x + b.x, a.y + b.y, a.z + b.z, a.w + b.w);
}

// -----------------------------------------------------------------------------
extern "C" void kernel_launch(void* const* d_in, const int* in_sizes, int n_in,
                              void* d_out, int out_size) {
    const float* x  = (const float*)d_in[0];
    const float* Wg = (const float*)d_in[1];
    const float* bg = (const float*)d_in[2];
    const float* W1 = (const float*)d_in[3];
    const float* b1 = (const float*)d_in[4];
    const float* W2 = (const float*)d_in[5];
    const float* b2 = (const float*)d_in[6];
    float* out = (float*)d_out;

    __half *ahi, *alo, *hp, *w1p, *w2p;
    cudaGetSymbolAddress((void**)&ahi, g_ahi); cudaGetSymbolAddress((void**)&alo, g_alo);
    cudaGetSymbolAddress((void**)&hp, g_h);
    cudaGetSymbolAddress((void**)&w1p, g_w1);  cudaGetSymbolAddress((void**)&w2p, g_w2);

    constexpr int DSM1 = 2 * 3 * MATB + 512 + 16;
    constexpr int DSM2 = 2 * 2 * MATB + 512 + 16;
    cudaFuncSetAttribute(k_mma<DDIM, FDIM, true, true>,   cudaFuncAttributeMaxDynamicSharedMemorySize, DSM1);
    cudaFuncSetAttribute(k_mma<FDIM, DDIM, false, false>, cudaFuncAttributeMaxDynamicSharedMemorySize, DSM2);

    k_reset<<<1, 32>>>();
    k_gate<<<NTOK, 128>>>(x, Wg, bg);
    k_offsets<<<1, 32>>>();
    k_pack<<<RPAD, 128>>>(x);
    k_tr<DDIM, FDIM><<<dim3(FDIM / 32, DDIM / 32, NEXP), dim3(32, 8)>>>(W1, w1p);
    k_tr<FDIM, DDIM><<<dim3(DDIM / 32, FDIM / 32, NEXP), dim3(32, 8)>>>(W2, w2p);

    dim3 g1(RPAD / 128, FDIM / 128);   // (132, 32)
    k_mma<DDIM, FDIM, true, true><<<g1, 256, DSM1>>>(ahi, alo, w1p, b1);
    dim3 g2(RPAD / 128, DDIM / 128);   // (132, 8)
    k_mma<FDIM, DDIM, false, false><<<g2, 256, DSM2>>>(hp, nullptr, w2p, b2);

    int nvec = NTOK * DDIM / 4;
    k_combine<<<(nvec + 255) / 256, 256>>>(out);
}